// round 4
// baseline (speedup 1.0000x reference)
#include <cuda_runtime.h>

#define L_Q   1024
#define B_Q   64
#define D_Q   512
#define U_Q   20
#define LTOT  3072                 // 3*L
#define NFRAG 7
#define FLEN  439                  // ceil(3072/7); 7*439 = 3073, pad = 1
#define NCH   (NFRAG * B_Q)        // 448 independent scan chains
#define SCAN_CHB 8                 // chains per scan block (static smem 28.2 KB)

// GEMM tiling
#define GR    256                  // rows per block
#define KC    16                   // k per chunk
#define NCHK  (D_Q / KC)           // 32 chunks
#define ROWF  20                   // floats per staged row (16 data + 4 pad)
#define W_FL  (D_Q * U_Q)          // 10240 floats
#define BUF_FL (GR * ROWF)         // 5120 floats per buffer
#define GEMM_SMEM ((W_FL + 2 * BUF_FL) * 4)   // 81920 B

// Scratch (no allocations allowed -> __device__ globals)
__device__ float2 g_c2[FLEN * NCH];                      // (c1, c2) per step, [ls][chain]
__device__ float  g_coords[(NFRAG * FLEN) * B_Q * 3];    // raw fragment coords [(f*FLEN+l)][b][3]
__device__ float4 g_Mt4[NFRAG * B_Q * 3];                // per (frag,b): [M00 M01 M02 M10][M11 M12 M20 M21][M22 tx ty tz]

// ---------- packed fp32 (Blackwell FFMA2) helpers ----------
static __device__ __forceinline__ unsigned long long dup2(float v) {
    unsigned long long r;
    asm("mov.b64 %0, {%1, %1};" : "=l"(r) : "f"(v));
    return r;
}
static __device__ __forceinline__ unsigned long long fma2(unsigned long long a,
                                                          unsigned long long b,
                                                          unsigned long long c) {
    unsigned long long d;
    asm("fma.rn.f32x2 %0, %1, %2, %3;" : "=l"(d) : "l"(a), "l"(b), "l"(c));
    return d;
}
static __device__ __forceinline__ float2 unpk(unsigned long long v) {
    float2 r;
    asm("mov.b64 {%0, %1}, %2;" : "=f"(r.x), "=f"(r.y) : "l"(v));
    return r;
}

// ---------- mbarrier / bulk-async helpers ----------
static __device__ __forceinline__ unsigned smem_u32(const void* p) {
    return (unsigned)__cvta_generic_to_shared(p);
}
static __device__ __forceinline__ void mbar_init(unsigned mb, unsigned cnt) {
    asm volatile("mbarrier.init.shared.b64 [%0], %1;" :: "r"(mb), "r"(cnt) : "memory");
}
static __device__ __forceinline__ void mbar_expect(unsigned mb, unsigned bytes) {
    asm volatile("mbarrier.arrive.expect_tx.shared.b64 _, [%0], %1;"
                 :: "r"(mb), "r"(bytes) : "memory");
}
static __device__ __forceinline__ void mbar_wait(unsigned mb, unsigned phase) {
    asm volatile(
        "{\n\t.reg .pred P;\n\t"
        "WLOOP_%=:\n\t"
        "mbarrier.try_wait.parity.acquire.cta.shared::cta.b64 P, [%0], %1, 0x989680;\n\t"
        "@!P bra WLOOP_%=;\n\t}"
        :: "r"(mb), "r"(phase) : "memory");
}
static __device__ __forceinline__ void bulk_g2s(unsigned dst, const void* src,
                                                unsigned bytes, unsigned mb) {
    asm volatile(
        "cp.async.bulk.shared::cluster.global.mbarrier::complete_tx::bytes [%0], [%1], %2, [%3];"
        :: "r"(dst), "l"(src), "r"(bytes), "r"(mb) : "memory");
}

// =====================================================================
// Kernel 1: logits GEMM (65536 x 512 x 20) + softmax-free angularization.
// A staged via cp.async.bulk (64B/row/chunk, double-buffered mbarrier
// pipeline) -> no per-lane L1tex wavefronts, full-line DRAM. 80B smem row
// stride -> 4-way LDS conflict only. W consumed as LDS.128 broadcasts.
// 2 rows/thread, 1024 warps chip-wide; FFMA2 accumulate (same FP order
// as previous rounds).
// =====================================================================
__global__ __launch_bounds__(128) void k_gemm(
    const float* __restrict__ inp, const float* __restrict__ W,
    const float* __restrict__ bias, const float* __restrict__ alpha,
    const float* __restrict__ bl, const float* __restrict__ ba)
{
    extern __shared__ float sm[];                        // [W_FL | buf0 | buf1]
    __shared__ __align__(8) unsigned long long mbar[2];
    __shared__ float sSin[U_Q * 3], sCos[U_Q * 3], sB[U_Q];
    int tid = threadIdx.x;

    // W transposed into smem: sW[k][u]
    for (int idx = tid; idx < W_FL; idx += 128) {
        int u = idx >> 9, k = idx & (D_Q - 1);
        sm[k * U_Q + u] = W[idx];
    }
    if (tid < U_Q * 3) { float a = alpha[tid]; sSin[tid] = sinf(a); sCos[tid] = cosf(a); }
    if (tid < U_Q) sB[tid] = bias[tid];
    if (tid == 0) { mbar_init(smem_u32(&mbar[0]), 1); mbar_init(smem_u32(&mbar[1]), 1); }

    // pNeRF pad element (global position 3072 -> frag 6, step ls=438):
    // its coordinate is dropped and its frame never consumed.
    if (blockIdx.x == 0 && tid < B_Q) {
        g_c2[(FLEN - 1) * NCH + 6 * B_Q + tid] = make_float2(0.1f, 0.1f);
    }
    __syncthreads();

    float rs[3];
#pragma unroll
    for (int j = 0; j < 3; j++) rs[j] = bl[j] * sinf(ba[j]);

    int w  = tid >> 5, lane = tid & 31;
    int raL = w * 64 + lane;                             // lanes own consecutive rows
    int rbL = raL + 32;
    int row0 = blockIdx.x * GR;
    unsigned sA0 = smem_u32(sm + W_FL);                  // buffer 0 base (smem u32)

    // issue chunk c into buffer c&1 (rows tid and tid+128, 64B each)
    const float* gsrc = inp + (size_t)row0 * D_Q;
#define ISSUE(c)                                                              \
    {                                                                         \
        int _buf = (c) & 1;                                                   \
        unsigned _mb = smem_u32(&mbar[_buf]);                                 \
        if (tid == 0) mbar_expect(_mb, GR * KC * 4);                          \
        unsigned _dst = sA0 + (unsigned)(_buf * BUF_FL + tid * ROWF) * 4u;    \
        bulk_g2s(_dst, gsrc + (size_t)tid * D_Q + (c) * KC, KC * 4, _mb);     \
        bulk_g2s(_dst + 128u * ROWF * 4u,                                     \
                 gsrc + (size_t)(tid + 128) * D_Q + (c) * KC, KC * 4, _mb);   \
    }

    ISSUE(0)
    ISSUE(1)

    unsigned long long acc[2][10];
#pragma unroll
    for (int r = 0; r < 2; r++)
#pragma unroll
        for (int p = 0; p < 10; p++) acc[r][p] = 0ull;

    for (int c = 0; c < NCHK; ++c) {
        int buf = c & 1;
        mbar_wait(smem_u32(&mbar[buf]), (c >> 1) & 1);

        const float* bufA = sm + W_FL + buf * BUF_FL;
        const float4* pa = (const float4*)(bufA + raL * ROWF);
        const float4* pb = (const float4*)(bufA + rbL * ROWF);
        const float* wk = sm + c * KC * U_Q;
#pragma unroll
        for (int q = 0; q < 4; ++q) {
            float4 a0 = pa[q];
            float4 a1 = pb[q];
#pragma unroll
            for (int kk = 0; kk < 4; ++kk) {
                const ulonglong2* wr = (const ulonglong2*)(wk + (q * 4 + kk) * U_Q);
                ulonglong2 w0 = wr[0], w1 = wr[1], w2 = wr[2], w3 = wr[3], w4 = wr[4];
                unsigned long long v0 = dup2(((const float*)&a0)[kk]);
                unsigned long long v1 = dup2(((const float*)&a1)[kk]);
                acc[0][0] = fma2(v0, w0.x, acc[0][0]); acc[1][0] = fma2(v1, w0.x, acc[1][0]);
                acc[0][1] = fma2(v0, w0.y, acc[0][1]); acc[1][1] = fma2(v1, w0.y, acc[1][1]);
                acc[0][2] = fma2(v0, w1.x, acc[0][2]); acc[1][2] = fma2(v1, w1.x, acc[1][2]);
                acc[0][3] = fma2(v0, w1.y, acc[0][3]); acc[1][3] = fma2(v1, w1.y, acc[1][3]);
                acc[0][4] = fma2(v0, w2.x, acc[0][4]); acc[1][4] = fma2(v1, w2.x, acc[1][4]);
                acc[0][5] = fma2(v0, w2.y, acc[0][5]); acc[1][5] = fma2(v1, w2.y, acc[1][5]);
                acc[0][6] = fma2(v0, w3.x, acc[0][6]); acc[1][6] = fma2(v1, w3.x, acc[1][6]);
                acc[0][7] = fma2(v0, w3.y, acc[0][7]); acc[1][7] = fma2(v1, w3.y, acc[1][7]);
                acc[0][8] = fma2(v0, w4.x, acc[0][8]); acc[1][8] = fma2(v1, w4.x, acc[1][8]);
                acc[0][9] = fma2(v0, w4.y, acc[0][9]); acc[1][9] = fma2(v1, w4.y, acc[1][9]);
            }
        }
        __syncthreads();                                 // everyone done with buf
        if (c + 2 < NCHK) ISSUE(c + 2)
    }
#undef ISSUE

#pragma unroll
    for (int r = 0; r < 2; r++) {
        float lg[U_Q];
#pragma unroll
        for (int p = 0; p < 10; p++) { float2 t = unpk(acc[r][p]); lg[2*p] = t.x; lg[2*p+1] = t.y; }
        float mx = -1e30f;
#pragma unroll
        for (int u = 0; u < U_Q; u++) { lg[u] += sB[u]; mx = fmaxf(mx, lg[u]); }
        // softmax numerator only: cos/sin(phi) from (s,c) ratio; softmax
        // normalization cancels.
        float sj[3] = {0.f,0.f,0.f}, cj[3] = {0.f,0.f,0.f};
#pragma unroll
        for (int u = 0; u < U_Q; u++) {
            float e = __expf(lg[u] - mx);
#pragma unroll
            for (int j = 0; j < 3; j++) {
                sj[j] = fmaf(e, sSin[u*3+j], sj[j]);
                cj[j] = fmaf(e, sCos[u*3+j], cj[j]);
            }
        }
        int row = row0 + (r == 0 ? raL : rbL);
        int l = row >> 6, b = row & 63;
#pragma unroll
        for (int j = 0; j < 3; j++) {
            float s = sj[j], c2v = cj[j];
            float rn = rsqrtf(fmaf(s, s, c2v * c2v));
            int m  = 3 * l + j;
            int f  = m / FLEN;
            int ls = m - f * FLEN;
            g_c2[ls * NCH + f * B_Q + b] =
                make_float2(rs[j] * (c2v * rn), rs[j] * (s * rn));
        }
    }
}

// =====================================================================
// Kernel 2: pNeRF scan, unit-frame recurrence with Newton-corrected
// normalization (stable: correction error squared each step).
// =====================================================================
__global__ __launch_bounds__(64) void k_scan(const float* __restrict__ bl,
                                             const float* __restrict__ ba)
{
    __shared__ float2 sc[(FLEN + 2) * SCAN_CHB];         // 28.2 KB static
    int tid = threadIdx.x;
    int chain0 = blockIdx.x * SCAN_CHB;
    for (int idx = tid; idx < (FLEN + 2) * SCAN_CHB; idx += 64) {
        int lsr = idx >> 3;
        int lane = idx & 7;
        sc[idx] = (lsr < FLEN) ? g_c2[lsr * NCH + chain0 + lane]
                               : make_float2(0.f, 0.f);
    }
    __syncthreads();
    if (tid >= SCAN_CHB) return;
    int chain = chain0 + tid;
    int f = chain >> 6, b = chain & 63;
    int ph = f % 3;

    float rcA[3], irA[3], nA[3], nB[3];
#pragma unroll
    for (int k = 0; k < 3; k++) {
        int j = ph + k; if (j >= 3) j -= 3;
        float r = bl[j], t = ba[j];
        rcA[k] = r * cosf(t);
        irA[k] = 1.f / r;
        float x0 = 1.f / (r * sinf(t));
        nA[k] = 1.5f * x0;
        nB[k] = 0.5f * x0 * x0 * x0;
    }

    float bcx = 1.f, bcy = 0.f, bcz = 0.f;
    float nx  = 0.f, ny  = 0.f, nz  = 1.f;
    float mhx = 0.f, mhy = 1.f, mhz = 0.f;
    float Cx = 0.f, Cy = 0.f, Cz = 0.f;

    float* outp = &g_coords[(((size_t)f * FLEN) * B_Q + b) * 3];
    const float2* pp = sc + tid;
    int l = 0;

#define SCAN_STEP(k)                                                         \
    {                                                                        \
        float2 cc = pp[l * SCAN_CHB];                                        \
        float dx = fmaf(cc.x, mhx, fmaf(cc.y, nx, rcA[k] * bcx));            \
        float dy = fmaf(cc.x, mhy, fmaf(cc.y, ny, rcA[k] * bcy));            \
        float dz = fmaf(cc.x, mhz, fmaf(cc.y, nz, rcA[k] * bcz));            \
        float Nx = fmaf(bcy, dz, -(bcz * dy));                               \
        float Ny = fmaf(bcz, dx, -(bcx * dz));                               \
        float Nz = fmaf(bcx, dy, -(bcy * dx));                               \
        float d2 = fmaf(Nx, Nx, fmaf(Ny, Ny, Nz * Nz));                      \
        float sfac = fmaf(d2, -nB[k], nA[k]);                                \
        nx = Nx * sfac; ny = Ny * sfac; nz = Nz * sfac;                      \
        bcx = dx * irA[k]; bcy = dy * irA[k]; bcz = dz * irA[k];             \
        mhx = fmaf(ny, bcz, -(nz * bcy));                                    \
        mhy = fmaf(nz, bcx, -(nx * bcz));                                    \
        mhz = fmaf(nx, bcy, -(ny * bcx));                                    \
        Cx += dx; Cy += dy; Cz += dz;                                        \
        float* o = outp + (size_t)l * (B_Q * 3);                             \
        o[0] = Cx; o[1] = Cy; o[2] = Cz;                                     \
        ++l;                                                                 \
    }

    for (int it = 0; it < 146; ++it) { SCAN_STEP(0) SCAN_STEP(1) SCAN_STEP(2) }
    SCAN_STEP(0)                                         // 439 = 3*146 + 1
#undef SCAN_STEP
}

// =====================================================================
// Kernel 3a: per-batch cumulative fragment transforms (composed affine).
// =====================================================================
__global__ void k_align()
{
    int b = threadIdx.x;
    if (b >= B_Q) return;
    float M00=1.f,M01=0.f,M02=0.f,M10=0.f,M11=1.f,M12=0.f,M20=0.f,M21=0.f,M22=1.f;
    float tx=0.f,ty=0.f,tz=0.f;
    {
        float4* mt = &g_Mt4[(size_t)b * 3];
        mt[0] = make_float4(1.f,0.f,0.f,0.f);
        mt[1] = make_float4(1.f,0.f,0.f,0.f);
        mt[2] = make_float4(1.f,0.f,0.f,0.f);
    }
    for (int j = 0; j < NFRAG - 1; ++j) {
        const float* A = &g_coords[(((size_t)j * FLEN + (FLEN - 3)) * B_Q + b) * 3];
        const float* Bv = A + B_Q * 3;
        const float* Cv = Bv + B_Q * 3;
        float bx=Cv[0]-Bv[0], by=Cv[1]-Bv[1], bz=Cv[2]-Bv[2];
        float ax=Bv[0]-A[0],  ay=Bv[1]-A[1],  az=Bv[2]-A[2];
        float Nx=fmaf(ay,bz,-az*by), Ny=fmaf(az,bx,-ax*bz), Nz=fmaf(ax,by,-ay*bx);
        float s1=rsqrtf(fmaf(bx,bx,fmaf(by,by,bz*bz)));
        float s2=rsqrtf(fmaf(Nx,Nx,fmaf(Ny,Ny,Nz*Nz)));
        float s12=s1*s2;
        float mxv=fmaf(Ny,bz,-Nz*by)*s12;
        float myv=fmaf(Nz,bx,-Nx*bz)*s12;
        float mzv=fmaf(Nx,by,-Ny*bx)*s12;
        float bcx=bx*s1, bcy=by*s1, bcz=bz*s1;
        float nx=Nx*s2,  ny=Ny*s2,  nz=Nz*s2;
        float N00 = M00*bcx + M01*bcy + M02*bcz;
        float N10 = M10*bcx + M11*bcy + M12*bcz;
        float N20 = M20*bcx + M21*bcy + M22*bcz;
        float N01 = M00*mxv + M01*myv + M02*mzv;
        float N11 = M10*mxv + M11*myv + M12*mzv;
        float N21 = M20*mxv + M21*myv + M22*mzv;
        float N02 = M00*nx + M01*ny + M02*nz;
        float N12 = M10*nx + M11*ny + M12*nz;
        float N22 = M20*nx + M21*ny + M22*nz;
        float ntx = tx + M00*Cv[0] + M01*Cv[1] + M02*Cv[2];
        float nty = ty + M10*Cv[0] + M11*Cv[1] + M12*Cv[2];
        float ntz = tz + M20*Cv[0] + M21*Cv[1] + M22*Cv[2];
        M00=N00;M01=N01;M02=N02;M10=N10;M11=N11;M12=N12;M20=N20;M21=N21;M22=N22;
        tx=ntx;ty=nty;tz=ntz;
        float4* mt = &g_Mt4[((size_t)(j + 1) * B_Q + b) * 3];
        mt[0] = make_float4(M00,M01,M02,M10);
        mt[1] = make_float4(M11,M12,M20,M21);
        mt[2] = make_float4(M22,tx,ty,tz);
    }
}

// =====================================================================
// Kernel 3b: apply per-fragment affine; b-pair per thread (float2 IO),
// 384 blocks for latency hiding.
// =====================================================================
__global__ __launch_bounds__(256) void k_out(float* __restrict__ out)
{
    int t = blockIdx.x * 256 + threadIdx.x;              // t < 98304
    int m = t >> 5;
    int b0 = (t & 31) * 2;
    int f = m / FLEN;
    const float2* X = (const float2*)&g_coords[((size_t)m * B_Q + b0) * 3];
    float2 x0 = X[0], x1 = X[1], x2 = X[2];
    const float4* Ma = &g_Mt4[((size_t)f * B_Q + b0) * 3];
    float4 a0 = Ma[0], a1 = Ma[1], a2 = Ma[2];
    float4 b0v = Ma[3], b1v = Ma[4], b2v = Ma[5];
    float r0x = fmaf(a0.x, x0.x, fmaf(a0.y, x0.y, fmaf(a0.z, x1.x, a2.y)));
    float r0y = fmaf(a0.w, x0.x, fmaf(a1.x, x0.y, fmaf(a1.y, x1.x, a2.z)));
    float r0z = fmaf(a1.z, x0.x, fmaf(a1.w, x0.y, fmaf(a2.x, x1.x, a2.w)));
    float r1x = fmaf(b0v.x, x1.y, fmaf(b0v.y, x2.x, fmaf(b0v.z, x2.y, b2v.y)));
    float r1y = fmaf(b0v.w, x1.y, fmaf(b1v.x, x2.x, fmaf(b1v.y, x2.y, b2v.z)));
    float r1z = fmaf(b1v.z, x1.y, fmaf(b1v.w, x2.x, fmaf(b2v.x, x2.y, b2v.w)));
    float2* O = (float2*)(out + ((size_t)m * B_Q + b0) * 3);
    O[0] = make_float2(r0x, r0y);
    O[1] = make_float2(r0z, r1x);
    O[2] = make_float2(r1y, r1z);
}

extern "C" void kernel_launch(void* const* d_in, const int* in_sizes, int n_in,
                              void* d_out, int out_size)
{
    (void)in_sizes; (void)n_in; (void)out_size;
    const float* inp   = (const float*)d_in[0];
    const float* W     = (const float*)d_in[1];
    const float* bias  = (const float*)d_in[2];
    const float* alpha = (const float*)d_in[3];
    const float* bl    = (const float*)d_in[4];
    const float* ba    = (const float*)d_in[5];
    // d_in[6] = nfrag (== 7 by construction; compile-time constant here)

    static int attr_done = 0;
    if (!attr_done) {
        cudaFuncSetAttribute(k_gemm, cudaFuncAttributeMaxDynamicSharedMemorySize, GEMM_SMEM);
        attr_done = 1;
    }

    k_gemm <<<256, 128, GEMM_SMEM>>>(inp, W, bias, alpha, bl, ba);
    k_scan <<<NCH / SCAN_CHB, 64>>>(bl, ba);              // 56 blocks * 8 chains
    k_align<<<1, 64>>>();
    k_out  <<<384, 256>>>((float*)d_out);                 // 98304 thr * b-pair
}

// round 5
// speedup vs baseline: 1.6083x; 1.6083x over previous
#include <cuda_runtime.h>

#define L_Q   1024
#define B_Q   64
#define D_Q   512
#define U_Q   20
#define LTOT  3072                 // 3*L
#define NFRAG 7
#define FLEN  439                  // ceil(3072/7); 7*439 = 3073, pad = 1
#define NCH   (NFRAG * B_Q)        // 448 independent scan chains
#define SCAN_CHB 8                 // chains per scan block (static smem 28.2 KB)

// GEMM tiling: 128 blocks x 256 threads, 512 rows/block, 2 rows/thread
#define GR    512                  // rows per block
#define KC    16                   // k per chunk
#define NCHK  (D_Q / KC)           // 32 chunks
#define ROWF  20                   // floats per staged row (16 data + 4 pad, 80B stride)
#define W_FL  (D_Q * U_Q)          // 10240 floats
#define BUF_FL (GR * ROWF)         // 10240 floats per buffer
#define GEMM_SMEM ((W_FL + 2 * BUF_FL) * 4)   // 122880 B

// Scratch (no allocations allowed -> __device__ globals)
__device__ float2 g_c2[FLEN * NCH];                      // (c1, c2) per step, [ls][chain]
__device__ float  g_coords[(NFRAG * FLEN) * B_Q * 3];    // raw fragment coords [(f*FLEN+l)][b][3]
__device__ float4 g_Mt4[NFRAG * B_Q * 3];                // per (frag,b): [M00 M01 M02 M10][M11 M12 M20 M21][M22 tx ty tz]

// ---------- packed fp32 (Blackwell FFMA2) helpers ----------
static __device__ __forceinline__ unsigned long long dup2(float v) {
    unsigned long long r;
    asm("mov.b64 %0, {%1, %1};" : "=l"(r) : "f"(v));
    return r;
}
static __device__ __forceinline__ unsigned long long fma2(unsigned long long a,
                                                          unsigned long long b,
                                                          unsigned long long c) {
    unsigned long long d;
    asm("fma.rn.f32x2 %0, %1, %2, %3;" : "=l"(d) : "l"(a), "l"(b), "l"(c));
    return d;
}
static __device__ __forceinline__ float2 unpk(unsigned long long v) {
    float2 r;
    asm("mov.b64 {%0, %1}, %2;" : "=f"(r.x), "=f"(r.y) : "l"(v));
    return r;
}
static __device__ __forceinline__ unsigned smem_u32(const void* p) {
    return (unsigned)__cvta_generic_to_shared(p);
}
static __device__ __forceinline__ void cp16(unsigned dst, const void* src) {
    asm volatile("cp.async.cg.shared.global [%0], [%1], 16;"
                 :: "r"(dst), "l"(src) : "memory");
}

// =====================================================================
// Kernel 1: logits GEMM (65536 x 512 x 20) + softmax-free angularization.
// A staged per chunk via per-thread cp.async (16B granules, coalesced:
// a warp covers 8 rows x 64B), double-buffered with commit/wait_group.
// Padded 80B smem row stride -> conflict-free LDS.128. W consumed as
// broadcast LDS.128 (5 per k-step). 2 rows/thread, FFMA2 accumulate.
// =====================================================================
__global__ __launch_bounds__(256) void k_gemm(
    const float* __restrict__ inp, const float* __restrict__ W,
    const float* __restrict__ bias, const float* __restrict__ alpha,
    const float* __restrict__ bl, const float* __restrict__ ba)
{
    extern __shared__ float sm[];                        // [W_FL | buf0 | buf1]
    __shared__ float sSin[U_Q * 3], sCos[U_Q * 3], sB[U_Q];
    int tid = threadIdx.x;

    // W transposed into smem: sW[k][u]
    for (int idx = tid; idx < W_FL; idx += 256) {
        int u = idx >> 9, k = idx & (D_Q - 1);
        sm[k * U_Q + u] = W[idx];
    }
    if (tid < U_Q * 3) { float a = alpha[tid]; sSin[tid] = sinf(a); sCos[tid] = cosf(a); }
    if (tid < U_Q) sB[tid] = bias[tid];

    // pNeRF pad element (global position 3072 -> frag 6, step ls=438):
    // its coordinate is dropped and its frame never consumed.
    if (blockIdx.x == 0 && tid < B_Q) {
        g_c2[(FLEN - 1) * NCH + 6 * B_Q + tid] = make_float2(0.1f, 0.1f);
    }

    float rs[3];
#pragma unroll
    for (int j = 0; j < 3; j++) rs[j] = bl[j] * sinf(ba[j]);

    int row0 = blockIdx.x * GR;
    const float* gsrc = inp + (size_t)row0 * D_Q;
    unsigned sA0 = smem_u32(sm + W_FL);

    // issue chunk c into buffer c&1: 512 rows x 64B, 8 cp.async/thread
#define ISSUE(c)                                                              \
    {                                                                         \
        unsigned _base = sA0 + (unsigned)(((c) & 1) * BUF_FL) * 4u;           \
        const float* _gs = gsrc + (c) * KC;                                   \
        _Pragma("unroll")                                                     \
        for (int i = 0; i < 8; i++) {                                         \
            int _idx = i * 256 + tid;                                         \
            int _row = _idx >> 2, _quad = _idx & 3;                           \
            cp16(_base + (unsigned)(_row * ROWF + _quad * 4) * 4u,            \
                 _gs + (size_t)_row * D_Q + _quad * 4);                       \
        }                                                                     \
        asm volatile("cp.async.commit_group;" ::: "memory");                  \
    }

    ISSUE(0)
    __syncthreads();                                     // covers W/sSin init too

    unsigned long long acc[2][10];
#pragma unroll
    for (int r = 0; r < 2; r++)
#pragma unroll
        for (int p = 0; p < 10; p++) acc[r][p] = 0ull;

    for (int c = 0; c < NCHK; ++c) {
        if (c + 1 < NCHK) {
            ISSUE(c + 1)
            asm volatile("cp.async.wait_group 1;" ::: "memory");
        } else {
            asm volatile("cp.async.wait_group 0;" ::: "memory");
        }
        __syncthreads();

        const float* bufA = sm + W_FL + (c & 1) * BUF_FL;
        float a0f[KC], a1f[KC];
#pragma unroll
        for (int q = 0; q < 4; ++q) {
            *(float4*)(a0f + q * 4) = ((const float4*)(bufA + tid * ROWF))[q];
            *(float4*)(a1f + q * 4) = ((const float4*)(bufA + (tid + 256) * ROWF))[q];
        }
        const float* wk = sm + c * KC * U_Q;
#pragma unroll
        for (int k = 0; k < KC; ++k) {
            const ulonglong2* wr = (const ulonglong2*)(wk + k * U_Q);
            ulonglong2 w0 = wr[0], w1 = wr[1], w2 = wr[2], w3 = wr[3], w4 = wr[4];
            unsigned long long v0 = dup2(a0f[k]);
            unsigned long long v1 = dup2(a1f[k]);
            acc[0][0] = fma2(v0, w0.x, acc[0][0]); acc[1][0] = fma2(v1, w0.x, acc[1][0]);
            acc[0][1] = fma2(v0, w0.y, acc[0][1]); acc[1][1] = fma2(v1, w0.y, acc[1][1]);
            acc[0][2] = fma2(v0, w1.x, acc[0][2]); acc[1][2] = fma2(v1, w1.x, acc[1][2]);
            acc[0][3] = fma2(v0, w1.y, acc[0][3]); acc[1][3] = fma2(v1, w1.y, acc[1][3]);
            acc[0][4] = fma2(v0, w2.x, acc[0][4]); acc[1][4] = fma2(v1, w2.x, acc[1][4]);
            acc[0][5] = fma2(v0, w2.y, acc[0][5]); acc[1][5] = fma2(v1, w2.y, acc[1][5]);
            acc[0][6] = fma2(v0, w3.x, acc[0][6]); acc[1][6] = fma2(v1, w3.x, acc[1][6]);
            acc[0][7] = fma2(v0, w3.y, acc[0][7]); acc[1][7] = fma2(v1, w3.y, acc[1][7]);
            acc[0][8] = fma2(v0, w4.x, acc[0][8]); acc[1][8] = fma2(v1, w4.x, acc[1][8]);
            acc[0][9] = fma2(v0, w4.y, acc[0][9]); acc[1][9] = fma2(v1, w4.y, acc[1][9]);
        }
        __syncthreads();                                 // buf reusable next iter
    }
#undef ISSUE

#pragma unroll
    for (int r = 0; r < 2; r++) {
        float lg[U_Q];
#pragma unroll
        for (int p = 0; p < 10; p++) { float2 t = unpk(acc[r][p]); lg[2*p] = t.x; lg[2*p+1] = t.y; }
        float mx = -1e30f;
#pragma unroll
        for (int u = 0; u < U_Q; u++) { lg[u] += sB[u]; mx = fmaxf(mx, lg[u]); }
        // softmax numerator only: cos/sin(phi) from (s,c) ratio; softmax
        // normalization cancels.
        float sj[3] = {0.f,0.f,0.f}, cj[3] = {0.f,0.f,0.f};
#pragma unroll
        for (int u = 0; u < U_Q; u++) {
            float e = __expf(lg[u] - mx);
#pragma unroll
            for (int j = 0; j < 3; j++) {
                sj[j] = fmaf(e, sSin[u*3+j], sj[j]);
                cj[j] = fmaf(e, sCos[u*3+j], cj[j]);
            }
        }
        int row = row0 + tid + r * 256;
        int l = row >> 6, b = row & 63;
#pragma unroll
        for (int j = 0; j < 3; j++) {
            float s = sj[j], c2v = cj[j];
            float rn = rsqrtf(fmaf(s, s, c2v * c2v));
            int m  = 3 * l + j;
            int f  = m / FLEN;
            int ls = m - f * FLEN;
            g_c2[ls * NCH + f * B_Q + b] =
                make_float2(rs[j] * (c2v * rn), rs[j] * (s * rn));
        }
    }
}

// =====================================================================
// Kernel 2: pNeRF scan; state (bc, N, sfac) with mh = sfac*(N x bc)
// folded in algebraically. Same stable Newton-corrected math as before,
// re-associated: recurrence latency 24 cyc, ~38 instr/step (issue-bound).
//   G = N x bc;  Y = c1*G + c2*N;  d = sfac*Y + rc*bc
//   bc' = d/r (analytic);  N' = bc x d;  sfac' = nA - nB*|N'|^2
// =====================================================================
__global__ __launch_bounds__(64) void k_scan(const float* __restrict__ bl,
                                             const float* __restrict__ ba)
{
    __shared__ float2 sc[(FLEN + 2) * SCAN_CHB];         // 28.2 KB static
    int tid = threadIdx.x;
    int chain0 = blockIdx.x * SCAN_CHB;
    for (int idx = tid; idx < (FLEN + 2) * SCAN_CHB; idx += 64) {
        int lsr = idx >> 3;
        int lane = idx & 7;
        sc[idx] = (lsr < FLEN) ? g_c2[lsr * NCH + chain0 + lane]
                               : make_float2(0.f, 0.f);
    }
    __syncthreads();
    if (tid >= SCAN_CHB) return;
    int chain = chain0 + tid;
    int f = chain >> 6, b = chain & 63;
    int ph = f % 3;

    float rcA[3], irA[3], nA[3], nB[3];
#pragma unroll
    for (int k = 0; k < 3; k++) {
        int j = ph + k; if (j >= 3) j -= 3;
        float r = bl[j], t = ba[j];
        rcA[k] = r * cosf(t);
        irA[k] = 1.f / r;
        float x0 = 1.f / (r * sinf(t));
        nA[k] = 1.5f * x0;
        nB[k] = 0.5f * x0 * x0 * x0;
    }

    // init: bc=(1,0,0), n=(0,0,1) -> N=(0,0,1), sfac=1 (mh=(0,1,0) implied)
    float bcx = 1.f, bcy = 0.f, bcz = 0.f;
    float Nx  = 0.f, Ny  = 0.f, Nz  = 1.f;
    float sfac = 1.f;
    float Cx = 0.f, Cy = 0.f, Cz = 0.f;

    float* outp = &g_coords[(((size_t)f * FLEN) * B_Q + b) * 3];
    const float2* pp = sc + tid;
    float2 pa = pp[0];
    float2 pb = pp[SCAN_CHB];
    int l = 0;

#define SCAN_STEP(k)                                                         \
    {                                                                        \
        float2 cc = pa; pa = pb; pb = pp[(l + 2) * SCAN_CHB];                \
        float Gx = fmaf(Ny, bcz, -(Nz * bcy));                               \
        float Gy = fmaf(Nz, bcx, -(Nx * bcz));                               \
        float Gz = fmaf(Nx, bcy, -(Ny * bcx));                               \
        float Yx = fmaf(cc.x, Gx, cc.y * Nx);                                \
        float Yy = fmaf(cc.x, Gy, cc.y * Ny);                                \
        float Yz = fmaf(cc.x, Gz, cc.y * Nz);                                \
        float dx = fmaf(sfac, Yx, rcA[k] * bcx);                             \
        float dy = fmaf(sfac, Yy, rcA[k] * bcy);                             \
        float dz = fmaf(sfac, Yz, rcA[k] * bcz);                             \
        float N2x = fmaf(bcy, dz, -(bcz * dy));                              \
        float N2y = fmaf(bcz, dx, -(bcx * dz));                              \
        float N2z = fmaf(bcx, dy, -(bcy * dx));                              \
        bcx = dx * irA[k]; bcy = dy * irA[k]; bcz = dz * irA[k];             \
        float d2 = fmaf(N2x, N2x, fmaf(N2y, N2y, N2z * N2z));                \
        sfac = fmaf(d2, -nB[k], nA[k]);                                      \
        Nx = N2x; Ny = N2y; Nz = N2z;                                        \
        Cx += dx; Cy += dy; Cz += dz;                                        \
        float* o = outp + (size_t)l * (B_Q * 3);                             \
        o[0] = Cx; o[1] = Cy; o[2] = Cz;                                     \
        ++l;                                                                 \
    }

    for (int it = 0; it < 146; ++it) { SCAN_STEP(0) SCAN_STEP(1) SCAN_STEP(2) }
    SCAN_STEP(0)                                         // 439 = 3*146 + 1
#undef SCAN_STEP
}

// =====================================================================
// Kernel 3a: per-batch cumulative fragment transforms (composed affine).
// =====================================================================
__global__ void k_align()
{
    int b = threadIdx.x;
    if (b >= B_Q) return;
    float M00=1.f,M01=0.f,M02=0.f,M10=0.f,M11=1.f,M12=0.f,M20=0.f,M21=0.f,M22=1.f;
    float tx=0.f,ty=0.f,tz=0.f;
    {
        float4* mt = &g_Mt4[(size_t)b * 3];
        mt[0] = make_float4(1.f,0.f,0.f,0.f);
        mt[1] = make_float4(1.f,0.f,0.f,0.f);
        mt[2] = make_float4(1.f,0.f,0.f,0.f);
    }
    for (int j = 0; j < NFRAG - 1; ++j) {
        const float* A = &g_coords[(((size_t)j * FLEN + (FLEN - 3)) * B_Q + b) * 3];
        const float* Bv = A + B_Q * 3;
        const float* Cv = Bv + B_Q * 3;
        float bx=Cv[0]-Bv[0], by=Cv[1]-Bv[1], bz=Cv[2]-Bv[2];
        float ax=Bv[0]-A[0],  ay=Bv[1]-A[1],  az=Bv[2]-A[2];
        float Nx=fmaf(ay,bz,-az*by), Ny=fmaf(az,bx,-ax*bz), Nz=fmaf(ax,by,-ay*bx);
        float s1=rsqrtf(fmaf(bx,bx,fmaf(by,by,bz*bz)));
        float s2=rsqrtf(fmaf(Nx,Nx,fmaf(Ny,Ny,Nz*Nz)));
        float s12=s1*s2;
        float mxv=fmaf(Ny,bz,-Nz*by)*s12;
        float myv=fmaf(Nz,bx,-Nx*bz)*s12;
        float mzv=fmaf(Nx,by,-Ny*bx)*s12;
        float bcx=bx*s1, bcy=by*s1, bcz=bz*s1;
        float nx=Nx*s2,  ny=Ny*s2,  nz=Nz*s2;
        float N00 = M00*bcx + M01*bcy + M02*bcz;
        float N10 = M10*bcx + M11*bcy + M12*bcz;
        float N20 = M20*bcx + M21*bcy + M22*bcz;
        float N01 = M00*mxv + M01*myv + M02*mzv;
        float N11 = M10*mxv + M11*myv + M12*mzv;
        float N21 = M20*mxv + M21*myv + M22*mzv;
        float N02 = M00*nx + M01*ny + M02*nz;
        float N12 = M10*nx + M11*ny + M12*nz;
        float N22 = M20*nx + M21*ny + M22*nz;
        float ntx = tx + M00*Cv[0] + M01*Cv[1] + M02*Cv[2];
        float nty = ty + M10*Cv[0] + M11*Cv[1] + M12*Cv[2];
        float ntz = tz + M20*Cv[0] + M21*Cv[1] + M22*Cv[2];
        M00=N00;M01=N01;M02=N02;M10=N10;M11=N11;M12=N12;M20=N20;M21=N21;M22=N22;
        tx=ntx;ty=nty;tz=ntz;
        float4* mt = &g_Mt4[((size_t)(j + 1) * B_Q + b) * 3];
        mt[0] = make_float4(M00,M01,M02,M10);
        mt[1] = make_float4(M11,M12,M20,M21);
        mt[2] = make_float4(M22,tx,ty,tz);
    }
}

// =====================================================================
// Kernel 3b: apply per-fragment affine; b-pair per thread (float2 IO).
// =====================================================================
__global__ __launch_bounds__(256) void k_out(float* __restrict__ out)
{
    int t = blockIdx.x * 256 + threadIdx.x;              // t < 98304
    int m = t >> 5;
    int b0 = (t & 31) * 2;
    int f = m / FLEN;
    const float2* X = (const float2*)&g_coords[((size_t)m * B_Q + b0) * 3];
    float2 x0 = X[0], x1 = X[1], x2 = X[2];
    const float4* Ma = &g_Mt4[((size_t)f * B_Q + b0) * 3];
    float4 a0 = Ma[0], a1 = Ma[1], a2 = Ma[2];
    float4 b0v = Ma[3], b1v = Ma[4], b2v = Ma[5];
    float r0x = fmaf(a0.x, x0.x, fmaf(a0.y, x0.y, fmaf(a0.z, x1.x, a2.y)));
    float r0y = fmaf(a0.w, x0.x, fmaf(a1.x, x0.y, fmaf(a1.y, x1.x, a2.z)));
    float r0z = fmaf(a1.z, x0.x, fmaf(a1.w, x0.y, fmaf(a2.x, x1.x, a2.w)));
    float r1x = fmaf(b0v.x, x1.y, fmaf(b0v.y, x2.x, fmaf(b0v.z, x2.y, b2v.y)));
    float r1y = fmaf(b0v.w, x1.y, fmaf(b1v.x, x2.x, fmaf(b1v.y, x2.y, b2v.z)));
    float r1z = fmaf(b1v.z, x1.y, fmaf(b1v.w, x2.x, fmaf(b2v.x, x2.y, b2v.w)));
    float2* O = (float2*)(out + ((size_t)m * B_Q + b0) * 3);
    O[0] = make_float2(r0x, r0y);
    O[1] = make_float2(r0z, r1x);
    O[2] = make_float2(r1y, r1z);
}

extern "C" void kernel_launch(void* const* d_in, const int* in_sizes, int n_in,
                              void* d_out, int out_size)
{
    (void)in_sizes; (void)n_in; (void)out_size;
    const float* inp   = (const float*)d_in[0];
    const float* W     = (const float*)d_in[1];
    const float* bias  = (const float*)d_in[2];
    const float* alpha = (const float*)d_in[3];
    const float* bl    = (const float*)d_in[4];
    const float* ba    = (const float*)d_in[5];
    // d_in[6] = nfrag (== 7 by construction; compile-time constant here)

    static int attr_done = 0;
    if (!attr_done) {
        cudaFuncSetAttribute(k_gemm, cudaFuncAttributeMaxDynamicSharedMemorySize, GEMM_SMEM);
        attr_done = 1;
    }

    k_gemm <<<128, 256, GEMM_SMEM>>>(inp, W, bias, alpha, bl, ba);
    k_scan <<<NCH / SCAN_CHB, 64>>>(bl, ba);              // 56 blocks * 8 chains
    k_align<<<1, 64>>>();
    k_out  <<<384, 256>>>((float*)d_out);                 // 98304 thr * b-pair
}